// round 1
// baseline (speedup 1.0000x reference)
#include <cuda_runtime.h>
#include <cstdint>

#define Bn 16
#define Cn 80
#define Hn 128
#define Wn 128
#define HWn 16384
#define Kn 100
#define NUMD 1000
#define SEGS 32
#define CAND_CAP 262144
#define SCORE_THR 0.05f
#define IOU_THR 0.5f
#define DIST_THR 0.5f

typedef unsigned long long u64;
typedef unsigned int u32;

// ---------------- device scratch ----------------
__device__ u64 g_cand[SEGS][CAND_CAP];
__device__ int g_cnt[SEGS];

__device__ float g_top_s[SEGS][Kn];
__device__ float g_top_x[SEGS][Kn];
__device__ float g_top_y[SEGS][Kn];
__device__ float g_top_e[SEGS][Kn];
__device__ int   g_top_c[SEGS][Kn];

__device__ float g_det_box[Bn][NUMD][4];
__device__ float g_det_sc[Bn][NUMD];
__device__ int   g_det_cls[Bn][NUMD];

// ---------------- helpers ----------------
__device__ __forceinline__ u32 map_f(float f) {
    u32 u = __float_as_uint(f);
    return (u & 0x80000000u) ? ~u : (u | 0x80000000u);
}
__device__ __forceinline__ float unmap_f(u32 m) {
    u32 b = (m & 0x80000000u) ? (m ^ 0x80000000u) : ~m;
    return __uint_as_float(b);
}
__device__ __forceinline__ float sigmoidf_dev(float x) {
    if (x >= 0.f) return 1.f / (1.f + expf(-x));
    float e = expf(x);
    return e / (1.f + e);
}

// ascending bitonic sort of n (power of 2) u64 keys in shared memory
__device__ __forceinline__ void bitonic_sort(u64* d, int n, int tid, int nt) {
    for (int k = 2; k <= n; k <<= 1) {
        for (int j = k >> 1; j > 0; j >>= 1) {
            for (int t = tid; t < n; t += nt) {
                int ixj = t ^ j;
                if (ixj > t) {
                    u64 a = d[t], b = d[ixj];
                    bool asc = ((t & k) == 0);
                    if ((a > b) == asc) { d[t] = b; d[ixj] = a; }
                }
            }
            __syncthreads();
        }
    }
}

// ---------------- K0: zero counters ----------------
__global__ void k_zero() {
    int t = threadIdx.x;
    if (t < SEGS) g_cnt[t] = 0;
}

// ---------------- K1: sigmoid + 3x3 local-max + candidate append ----------------
// one block per (heat, b, c) plane; 256 threads; 64KB dyn smem for the plane
__global__ void k_localmax(const float* __restrict__ tl, const float* __restrict__ br) {
    extern __shared__ float sm[];  // HWn floats
    const int plane = blockIdx.x;                // 0 .. 2*B*C-1
    const int h = plane / (Bn * Cn);
    const int rem = plane % (Bn * Cn);           // b*C + c
    const int b = rem / Cn;
    const int c = rem % Cn;
    const int seg = h * Bn + b;
    const float* src = (h == 0 ? tl : br) + (size_t)rem * HWn;

    const int tid = threadIdx.x;
    // coalesced load of plane into shared
    const float4* s4 = (const float4*)src;
    float4* d4 = (float4*)sm;
    for (int i = tid; i < HWn / 4; i += 256) d4[i] = s4[i];
    __syncthreads();

    const int lane = tid & 31;
    u64 lbuf[64];
    int lcnt = 0;

    for (int e = tid; e < HWn; e += 256) {
        int y = e >> 7, x = e & 127;
        float v = sm[e];
        int y0 = y > 0 ? y - 1 : 0;
        int y1 = y < 127 ? y + 1 : 127;
        int x0 = x > 0 ? x - 1 : 0;
        int x1 = x < 127 ? x + 1 : 127;
        bool mx = true;
        for (int yy = y0; yy <= y1; ++yy)
            for (int xx = x0; xx <= x1; ++xx)
                mx &= (v >= sm[yy * Wn + xx]);
        if (mx) {
            float s = sigmoidf_dev(v);
            u32 idx = (u32)(c * HWn + e);
            u64 key = ((u64)(__float_as_uint(s) | 0x80000000u) << 32) |
                      (u64)(0xFFFFFFFFu - idx);
            if (lcnt < 64) lbuf[lcnt++] = key;
        }
    }

    // warp-aggregated append
    // prefix over lanes of lcnt
    int total = lcnt;
    int pre = 0;
    for (int off = 1; off < 32; off <<= 1) {
        int v2 = __shfl_up_sync(0xffffffffu, total, off);
        if (lane >= off) total += v2;
    }
    // total now inclusive prefix; exclusive = total - lcnt
    pre = total - lcnt;
    int warpTotal = __shfl_sync(0xffffffffu, total, 31);
    int base = 0;
    if (lane == 0 && warpTotal > 0) base = atomicAdd(&g_cnt[seg], warpTotal);
    base = __shfl_sync(0xffffffffu, base, 0);
    for (int i = 0; i < lcnt; i++) {
        int pos = base + pre + i;
        if (pos < CAND_CAP) g_cand[seg][pos] = lbuf[i];
    }
}

// ---------------- K2: per-segment top-100 select + gather ----------------
// 32 blocks, 1024 threads, dyn smem: comp[16384] u64 + hist[4096] u32
__global__ void k_select(const float* __restrict__ tl_off, const float* __restrict__ br_off,
                         const float* __restrict__ tl_emb, const float* __restrict__ br_emb,
                         const int* __restrict__ inp_h, const int* __restrict__ inp_w) {
    extern __shared__ unsigned char s4[];
    u64* comp = (u64*)s4;                 // 16384
    u32* hist = (u32*)(comp + 16384);     // 4096
    __shared__ int s_cut, s_cnt2, chunk[32];

    const int seg = blockIdx.x;
    const int tid = threadIdx.x;
    const int Mc0 = g_cnt[seg];
    const int Mc = Mc0 < CAND_CAP ? Mc0 : CAND_CAP;

    for (int i = tid; i < 4096; i += 1024) hist[i] = 0;
    if (tid == 0) s_cnt2 = 0;
    __syncthreads();

    for (int i = tid; i < Mc; i += 1024)
        atomicAdd(&hist[(u32)(g_cand[seg][i] >> 52)], 1u);
    __syncthreads();

    if (tid < 32) {
        int s = 0;
        for (int i = 0; i < 128; i++) s += hist[tid * 128 + i];
        chunk[tid] = s;
    }
    __syncthreads();
    if (tid == 0) {
        int acc = 0, T = 0, w;
        for (w = 31; w >= 0; --w) {
            if (acc + chunk[w] >= Kn) break;
            acc += chunk[w];
        }
        if (w >= 0) {
            for (int bin = w * 128 + 127; bin >= w * 128; --bin) {
                acc += hist[bin];
                if (acc >= Kn) { T = bin; break; }
            }
        }
        s_cut = T;
    }
    __syncthreads();
    const u32 T = (u32)s_cut;

    for (int i = tid; i < Mc; i += 1024) {
        u64 key = g_cand[seg][i];
        if ((u32)(key >> 52) >= T) {
            int pos = atomicAdd(&s_cnt2, 1);
            if (pos < 16384) comp[pos] = key;
        }
    }
    __syncthreads();

    int cnt2 = s_cnt2 < 16384 ? s_cnt2 : 16384;
    int n2 = 128;
    while (n2 < cnt2) n2 <<= 1;
    for (int t = cnt2 + tid; t < n2; t += 1024) comp[t] = 0ull;
    __syncthreads();

    bitonic_sort(comp, n2, tid, 1024);

    if (tid < Kn) {
        u64 key = comp[n2 - 1 - tid];
        u32 m = (u32)(key >> 32);
        float score = __uint_as_float(m & 0x7FFFFFFFu);
        u32 idx = 0xFFFFFFFFu - (u32)(key & 0xFFFFFFFFu);
        int cls = idx / HWn;
        int ind = idx % HWn;
        int yy = ind >> 7, xx = ind & 127;
        int hflag = seg / Bn;
        int b = seg % Bn;
        const float* offp = hflag ? br_off : tl_off;
        const float* embp = hflag ? br_emb : tl_emb;
        float ox = offp[((size_t)(b * 2 + 0) * HWn) + ind];
        float oy = offp[((size_t)(b * 2 + 1) * HWn) + ind];
        float em = embp[(size_t)b * HWn + ind];
        float wr = (float)(*inp_w) / (float)Wn;
        float hr = (float)(*inp_h) / (float)Hn;
        float xs = fmaxf(((float)xx + ox) * wr, 0.f);
        float ys = fmaxf(((float)yy + oy) * hr, 0.f);
        g_top_s[seg][tid] = score;
        g_top_x[seg][tid] = xs;
        g_top_y[seg][tid] = ys;
        g_top_e[seg][tid] = em;
        g_top_c[seg][tid] = cls;
    }
}

// ---------------- K3: pairing + top-1000 per batch ----------------
// 16 blocks, 1024 threads, dyn smem: arr[16384] u64
__global__ void k_pair() {
    extern __shared__ u64 arr[];
    __shared__ float ts[Kn], tx[Kn], ty[Kn], te[Kn];
    __shared__ float bs_[Kn], bx[Kn], by[Kn], be[Kn];
    __shared__ int tc[Kn], bc[Kn];

    const int b = blockIdx.x;
    const int tid = threadIdx.x;
    if (tid < Kn) {
        int st = b, sb = Bn + b;
        ts[tid] = g_top_s[st][tid]; tx[tid] = g_top_x[st][tid];
        ty[tid] = g_top_y[st][tid]; te[tid] = g_top_e[st][tid];
        tc[tid] = g_top_c[st][tid];
        bs_[tid] = g_top_s[sb][tid]; bx[tid] = g_top_x[sb][tid];
        by[tid] = g_top_y[sb][tid]; be[tid] = g_top_e[sb][tid];
        bc[tid] = g_top_c[sb][tid];
    }
    __syncthreads();

    for (int t = tid; t < 16384; t += 1024) {
        u64 key = 0ull;
        if (t < Kn * Kn) {
            int i = t / Kn, j = t % Kn;
            float sc = (ts[i] + bs_[j]) * 0.5f;
            bool neg = (tc[i] != bc[j]) || (bx[j] <= tx[i]) || (by[j] <= ty[i]) ||
                       (fabsf(te[i] - be[j]) > DIST_THR);
            if (neg) sc = -1.0f;
            key = ((u64)map_f(sc) << 32) | (u64)(0xFFFFFFFFu - (u32)t);
        }
        arr[t] = key;
    }
    __syncthreads();

    bitonic_sort(arr, 16384, tid, 1024);

    for (int r = tid; r < NUMD; r += 1024) {
        u64 key = arr[16383 - r];
        u32 m = (u32)(key >> 32);
        float sc = unmap_f(m);
        u32 t = 0xFFFFFFFFu - (u32)(key & 0xFFFFFFFFu);
        int i = t / Kn, j = t % Kn;
        g_det_box[b][r][0] = tx[i];
        g_det_box[b][r][1] = ty[i];
        g_det_box[b][r][2] = bx[j];
        g_det_box[b][r][3] = by[j];
        g_det_sc[b][r] = sc;
        g_det_cls[b][r] = tc[i];
    }
}

// ---------------- K4: greedy NMS + output ----------------
__global__ void k_nms(float* __restrict__ out) {
    __shared__ float x1[NUMD], y1[NUMD], x2[NUMD], y2[NUMD], sc[NUMD], ar[NUMD];
    __shared__ int cl[NUMD];
    __shared__ unsigned char kp[NUMD];
    __shared__ int idxs[Kn];
    __shared__ int s_num;

    const int b = blockIdx.x;
    const int tid = threadIdx.x;

    for (int i = tid; i < NUMD; i += 256) {
        float a0 = g_det_box[b][i][0], a1 = g_det_box[b][i][1];
        float a2 = g_det_box[b][i][2], a3 = g_det_box[b][i][3];
        x1[i] = a0; y1[i] = a1; x2[i] = a2; y2[i] = a3;
        sc[i] = g_det_sc[b][i];
        cl[i] = g_det_cls[b][i];
        kp[i] = 1;
        ar[i] = fmaxf(a2 - a0, 0.f) * fmaxf(a3 - a1, 0.f);
    }
    __syncthreads();

    for (int i = 0; i < NUMD; i++) {
        if (sc[i] <= SCORE_THR) break;   // uniform: sorted descending
        if (!kp[i]) continue;            // uniform: shared value
        float xi1 = x1[i], yi1 = y1[i], xi2 = x2[i], yi2 = y2[i], ai = ar[i];
        int ci = cl[i];
        for (int j = i + 1 + tid; j < NUMD; j += 256) {
            if (kp[j] && cl[j] == ci) {
                float iw = fmaxf(fminf(xi2, x2[j]) - fmaxf(xi1, x1[j]), 0.f);
                float ih = fmaxf(fminf(yi2, y2[j]) - fmaxf(yi1, y1[j]), 0.f);
                float inter = iw * ih;
                float iou = inter / fmaxf(ai + ar[j] - inter, 1e-6f);
                if (iou > IOU_THR) kp[j] = 0;
            }
        }
        __syncthreads();
    }

    if (tid == 0) {
        int cnt = 0;
        for (int i = 0; i < NUMD; i++) {
            if (kp[i] && sc[i] > SCORE_THR) {
                if (cnt < Kn) idxs[cnt] = i;
                cnt++;
            }
        }
        s_num = cnt < Kn ? cnt : Kn;
        out[b] = (float)s_num;
    }
    __syncthreads();

    const int num = s_num;
    float* pb = out + Bn;                       // boxes
    float* ps = out + Bn + Bn * Kn * 4;         // scores
    float* pc = out + Bn + Bn * Kn * 4 + Bn * Kn; // classes
    for (int r = tid; r < Kn; r += 256) {
        float b0 = 0.f, b1 = 0.f, b2 = 0.f, b3 = 0.f, s = 0.f, c = -1.0f;
        if (r < num) {
            int i = idxs[r];
            b0 = x1[i]; b1 = y1[i]; b2 = x2[i]; b3 = y2[i];
            s = sc[i]; c = (float)cl[i];
        }
        size_t base = (size_t)(b * Kn + r);
        pb[base * 4 + 0] = b0;
        pb[base * 4 + 1] = b1;
        pb[base * 4 + 2] = b2;
        pb[base * 4 + 3] = b3;
        ps[base] = s;
        pc[base] = c;
    }
}

// ---------------- launch ----------------
extern "C" void kernel_launch(void* const* d_in, const int* in_sizes, int n_in,
                              void* d_out, int out_size) {
    const float* tl_heat = (const float*)d_in[0];
    const float* br_heat = (const float*)d_in[1];
    const float* tl_off  = (const float*)d_in[2];
    const float* br_off  = (const float*)d_in[3];
    const float* tl_emb  = (const float*)d_in[4];
    const float* br_emb  = (const float*)d_in[5];
    const int*   inp_h   = (const int*)d_in[6];
    const int*   inp_w   = (const int*)d_in[7];
    float* out = (float*)d_out;

    cudaFuncSetAttribute(k_localmax, cudaFuncAttributeMaxDynamicSharedMemorySize, HWn * 4);
    cudaFuncSetAttribute(k_select, cudaFuncAttributeMaxDynamicSharedMemorySize,
                         16384 * 8 + 4096 * 4);
    cudaFuncSetAttribute(k_pair, cudaFuncAttributeMaxDynamicSharedMemorySize, 16384 * 8);

    k_zero<<<1, 32>>>();
    k_localmax<<<2 * Bn * Cn, 256, HWn * 4>>>(tl_heat, br_heat);
    k_select<<<SEGS, 1024, 16384 * 8 + 4096 * 4>>>(tl_off, br_off, tl_emb, br_emb, inp_h, inp_w);
    k_pair<<<Bn, 1024, 16384 * 8>>>();
    k_nms<<<Bn, 256>>>(out);
}

// round 2
// speedup vs baseline: 2.1252x; 2.1252x over previous
#include <cuda_runtime.h>
#include <cstdint>

#define Bn 16
#define Cn 80
#define Hn 128
#define Wn 128
#define HWn 16384
#define Kn 100
#define NUMD 1000
#define SEGS 32
#define CAND_CAP 262144
#define SCORE_THR 0.05f
#define IOU_THR 0.5f
#define DIST_THR 0.5f

typedef unsigned long long u64;
typedef unsigned int u32;

#define NEG_INF __int_as_float(0xff800000)

// ---------------- device scratch ----------------
__device__ u64 g_cand[SEGS][CAND_CAP];
__device__ int g_cnt[SEGS];

__device__ float g_top_s[SEGS][Kn];
__device__ float g_top_x[SEGS][Kn];
__device__ float g_top_y[SEGS][Kn];
__device__ float g_top_e[SEGS][Kn];
__device__ int   g_top_c[SEGS][Kn];

// ---------------- helpers ----------------
__device__ __forceinline__ u32 map_f(float f) {
    u32 u = __float_as_uint(f);
    return (u & 0x80000000u) ? ~u : (u | 0x80000000u);
}
__device__ __forceinline__ float sigmoidf_dev(float x) {
    if (x >= 0.f) return 1.f / (1.f + expf(-x));
    float e = expf(x);
    return e / (1.f + e);
}

// ascending bitonic sort of n (power of 2) u64 keys in shared memory
__device__ __forceinline__ void bitonic_sort(u64* d, int n, int tid, int nt) {
    for (int k = 2; k <= n; k <<= 1) {
        for (int j = k >> 1; j > 0; j >>= 1) {
            for (int t = tid; t < n; t += nt) {
                int ixj = t ^ j;
                if (ixj > t) {
                    u64 a = d[t], b = d[ixj];
                    bool asc = ((t & k) == 0);
                    if ((a > b) == asc) { d[t] = b; d[ixj] = a; }
                }
            }
            __syncthreads();
        }
    }
}

// ---------------- K0: zero counters ----------------
__global__ void k_zero() {
    int t = threadIdx.x;
    if (t < SEGS) g_cnt[t] = 0;
}

// ---------------- K1: 3x3 local-max (separable, register-rolling) ----------------
// one block per (heat, b, c) plane; 256 threads = 8 warps x 16 rows each.
// Warp-per-row: lane holds float4 (128 cols / 32 lanes). Horizontal 3-max via
// shuffles; vertical 3-max by rolling 3 rows of hmax in registers. No smem.
__global__ void k_localmax(const float* __restrict__ tl, const float* __restrict__ br) {
    const int plane = blockIdx.x;                // 0 .. 2*B*C-1
    const int h = plane / (Bn * Cn);
    const int rem = plane % (Bn * Cn);           // b*C + c
    const int b = rem / Cn;
    const int c = rem % Cn;
    const int seg = h * Bn + b;
    const float* src = (h == 0 ? tl : br) + (size_t)rem * HWn;

    const int warp = threadIdx.x >> 5;
    const int lane = threadIdx.x & 31;
    const int r0 = warp * 16;

    const float4* row4 = (const float4*)src;

    float4 vcur, vnext;
    float4 hprev, hcur, hnext;

    // horizontal windowed max of a row held as float4 per lane
    auto hmax4 = [&](float4 v) -> float4 {
        float left  = __shfl_up_sync(0xffffffffu, v.w, 1);
        float right = __shfl_down_sync(0xffffffffu, v.x, 1);
        if (lane == 0)  left  = NEG_INF;
        if (lane == 31) right = NEG_INF;
        float4 r;
        r.x = fmaxf(fmaxf(left, v.x), v.y);
        r.y = fmaxf(fmaxf(v.x, v.y), v.z);
        r.z = fmaxf(fmaxf(v.y, v.z), v.w);
        r.w = fmaxf(fmaxf(v.z, v.w), right);
        return r;
    };

    // prime: row r0 and row r0-1
    vcur = row4[r0 * 32 + lane];
    hcur = hmax4(vcur);
    if (r0 > 0) {
        float4 vp = row4[(r0 - 1) * 32 + lane];
        hprev = hmax4(vp);
    } else {
        hprev = make_float4(NEG_INF, NEG_INF, NEG_INF, NEG_INF);
    }

    for (int y = r0; y < r0 + 16; ++y) {
        if (y + 1 < Hn) {
            vnext = row4[(y + 1) * 32 + lane];
            hnext = hmax4(vnext);
        } else {
            hnext = make_float4(NEG_INF, NEG_INF, NEG_INF, NEG_INF);
        }

        bool f0 = vcur.x >= fmaxf(fmaxf(hprev.x, hcur.x), hnext.x);
        bool f1 = vcur.y >= fmaxf(fmaxf(hprev.y, hcur.y), hnext.y);
        bool f2 = vcur.z >= fmaxf(fmaxf(hprev.z, hcur.z), hnext.z);
        bool f3 = vcur.w >= fmaxf(fmaxf(hprev.w, hcur.w), hnext.w);

        int cnt = (int)f0 + (int)f1 + (int)f2 + (int)f3;
        // inclusive prefix over lanes
        int inc = cnt;
        #pragma unroll
        for (int off = 1; off < 32; off <<= 1) {
            int v2 = __shfl_up_sync(0xffffffffu, inc, off);
            if (lane >= off) inc += v2;
        }
        int excl = inc - cnt;
        int tot = __shfl_sync(0xffffffffu, inc, 31);
        int base = 0;
        if (lane == 0 && tot > 0) base = atomicAdd(&g_cnt[seg], tot);
        base = __shfl_sync(0xffffffffu, base, 0);
        int p = base + excl;

        int xb = lane * 4;
        u32 idx_base = (u32)(c * HWn + y * Wn + xb);
        if (f0 && p < CAND_CAP) {
            float s = sigmoidf_dev(vcur.x);
            g_cand[seg][p++] = ((u64)(__float_as_uint(s) | 0x80000000u) << 32) |
                               (u64)(0xFFFFFFFFu - (idx_base + 0));
        }
        if (f1 && p < CAND_CAP) {
            float s = sigmoidf_dev(vcur.y);
            g_cand[seg][p++] = ((u64)(__float_as_uint(s) | 0x80000000u) << 32) |
                               (u64)(0xFFFFFFFFu - (idx_base + 1));
        }
        if (f2 && p < CAND_CAP) {
            float s = sigmoidf_dev(vcur.z);
            g_cand[seg][p++] = ((u64)(__float_as_uint(s) | 0x80000000u) << 32) |
                               (u64)(0xFFFFFFFFu - (idx_base + 2));
        }
        if (f3 && p < CAND_CAP) {
            float s = sigmoidf_dev(vcur.w);
            g_cand[seg][p++] = ((u64)(__float_as_uint(s) | 0x80000000u) << 32) |
                               (u64)(0xFFFFFFFFu - (idx_base + 3));
        }

        hprev = hcur; hcur = hnext; vcur = vnext;
    }
}

// ---------------- K2: per-segment top-100 select + gather ----------------
// 32 blocks, 1024 threads, dyn smem: comp[16384] u64 + hist[4096] u32
__global__ void k_select(const float* __restrict__ tl_off, const float* __restrict__ br_off,
                         const float* __restrict__ tl_emb, const float* __restrict__ br_emb,
                         const int* __restrict__ inp_h, const int* __restrict__ inp_w) {
    extern __shared__ unsigned char s4[];
    u64* comp = (u64*)s4;                 // 16384
    u32* hist = (u32*)(comp + 16384);     // 4096
    __shared__ int s_cut, s_cnt2, chunk[32];

    const int seg = blockIdx.x;
    const int tid = threadIdx.x;
    const int Mc0 = g_cnt[seg];
    const int Mc = Mc0 < CAND_CAP ? Mc0 : CAND_CAP;

    for (int i = tid; i < 4096; i += 1024) hist[i] = 0;
    if (tid == 0) s_cnt2 = 0;
    __syncthreads();

    for (int i = tid; i < Mc; i += 1024)
        atomicAdd(&hist[(u32)(g_cand[seg][i] >> 52)], 1u);
    __syncthreads();

    if (tid < 32) {
        int s = 0;
        for (int i = 0; i < 128; i++) s += hist[tid * 128 + i];
        chunk[tid] = s;
    }
    __syncthreads();
    if (tid == 0) {
        int acc = 0, T = 0, w;
        for (w = 31; w >= 0; --w) {
            if (acc + chunk[w] >= Kn) break;
            acc += chunk[w];
        }
        if (w >= 0) {
            for (int bin = w * 128 + 127; bin >= w * 128; --bin) {
                acc += hist[bin];
                if (acc >= Kn) { T = bin; break; }
            }
        }
        s_cut = T;
    }
    __syncthreads();
    const u32 T = (u32)s_cut;

    for (int i = tid; i < Mc; i += 1024) {
        u64 key = g_cand[seg][i];
        if ((u32)(key >> 52) >= T) {
            int pos = atomicAdd(&s_cnt2, 1);
            if (pos < 16384) comp[pos] = key;
        }
    }
    __syncthreads();

    int cnt2 = s_cnt2 < 16384 ? s_cnt2 : 16384;
    int n2 = 128;
    while (n2 < cnt2) n2 <<= 1;
    for (int t = cnt2 + tid; t < n2; t += 1024) comp[t] = 0ull;
    __syncthreads();

    bitonic_sort(comp, n2, tid, 1024);

    if (tid < Kn) {
        u64 key = comp[n2 - 1 - tid];
        u32 m = (u32)(key >> 32);
        float score = __uint_as_float(m & 0x7FFFFFFFu);
        u32 idx = 0xFFFFFFFFu - (u32)(key & 0xFFFFFFFFu);
        int cls = idx / HWn;
        int ind = idx % HWn;
        int yy = ind >> 7, xx = ind & 127;
        int hflag = seg / Bn;
        int b = seg % Bn;
        const float* offp = hflag ? br_off : tl_off;
        const float* embp = hflag ? br_emb : tl_emb;
        float ox = offp[((size_t)(b * 2 + 0) * HWn) + ind];
        float oy = offp[((size_t)(b * 2 + 1) * HWn) + ind];
        float em = embp[(size_t)b * HWn + ind];
        float wr = (float)(*inp_w) / (float)Wn;
        float hr = (float)(*inp_h) / (float)Hn;
        float xs = fmaxf(((float)xx + ox) * wr, 0.f);
        float ys = fmaxf(((float)yy + oy) * hr, 0.f);
        g_top_s[seg][tid] = score;
        g_top_x[seg][tid] = xs;
        g_top_y[seg][tid] = ys;
        g_top_e[seg][tid] = em;
        g_top_c[seg][tid] = cls;
    }
}

// ---------------- K3: pairing + compact positives + sort + NMS + output ----------------
// 16 blocks (one per batch), 256 threads. dyn smem: pos[16384] u64.
// Only pairs with score > SCORE_THR and not neg-masked can ever appear in the
// output or suppress anything (valid = score > thr in the reference, and all
// positives outrank all <=thr entries in the descending top-1000). So we
// compact positives only, sort them (tiny in practice, <= 16384 worst case),
// then run greedy NMS on the sorted prefix of length min(npos, 1000).
__global__ void k_pair_nms(float* __restrict__ out) {
    extern __shared__ u64 pos[];  // 16384 capacity
    __shared__ float ts[Kn], tx[Kn], ty[Kn], te[Kn];
    __shared__ float bs_[Kn], bx[Kn], by[Kn], be[Kn];
    __shared__ int tc[Kn], bc[Kn];
    __shared__ int s_np;

    __shared__ float x1[NUMD], y1[NUMD], x2[NUMD], y2[NUMD], sc[NUMD], ar[NUMD];
    __shared__ int cl[NUMD];
    __shared__ unsigned char kp[NUMD];
    __shared__ int idxs[Kn];
    __shared__ int s_num;

    const int b = blockIdx.x;
    const int tid = threadIdx.x;

    if (tid < Kn) {
        int st = b, sb = Bn + b;
        ts[tid] = g_top_s[st][tid]; tx[tid] = g_top_x[st][tid];
        ty[tid] = g_top_y[st][tid]; te[tid] = g_top_e[st][tid];
        tc[tid] = g_top_c[st][tid];
        bs_[tid] = g_top_s[sb][tid]; bx[tid] = g_top_x[sb][tid];
        by[tid] = g_top_y[sb][tid]; be[tid] = g_top_e[sb][tid];
        bc[tid] = g_top_c[sb][tid];
    }
    if (tid == 0) s_np = 0;
    __syncthreads();

    for (int t = tid; t < Kn * Kn; t += 256) {
        int i = t / Kn, j = t % Kn;
        float scv = (ts[i] + bs_[j]) * 0.5f;
        bool neg = (tc[i] != bc[j]) || (bx[j] <= tx[i]) || (by[j] <= ty[i]) ||
                   (fabsf(te[i] - be[j]) > DIST_THR);
        if (!neg && scv > SCORE_THR) {
            int p = atomicAdd(&s_np, 1);
            if (p < 16384)
                pos[p] = ((u64)map_f(scv) << 32) | (u64)(0xFFFFFFFFu - (u32)t);
        }
    }
    __syncthreads();

    int np = s_np < 16384 ? s_np : 16384;
    if (np > 0) {
        int n2 = 2;
        while (n2 < np) n2 <<= 1;
        for (int t = np + tid; t < n2; t += 256) pos[t] = 0ull;
        __syncthreads();
        bitonic_sort(pos, n2, tid, 256);

        int m = np < NUMD ? np : NUMD;
        for (int r = tid; r < m; r += 256) {
            u64 key = pos[n2 - 1 - r];
            u32 mm = (u32)(key >> 32);
            // positives always have sign bit set after map (score > 0)
            float scv = __uint_as_float(mm & 0x7FFFFFFFu);
            u32 t = 0xFFFFFFFFu - (u32)(key & 0xFFFFFFFFu);
            int i = t / Kn, j = t % Kn;
            float a0 = tx[i], a1 = ty[i], a2 = bx[j], a3 = by[j];
            x1[r] = a0; y1[r] = a1; x2[r] = a2; y2[r] = a3;
            sc[r] = scv;
            cl[r] = tc[i];
            kp[r] = 1;
            ar[r] = fmaxf(a2 - a0, 0.f) * fmaxf(a3 - a1, 0.f);
        }
        __syncthreads();

        // greedy NMS over m sorted valid detections
        for (int i = 0; i < m; i++) {
            if (kp[i]) {
                float xi1 = x1[i], yi1 = y1[i], xi2 = x2[i], yi2 = y2[i], ai = ar[i];
                int ci = cl[i];
                for (int j = i + 1 + tid; j < m; j += 256) {
                    if (kp[j] && cl[j] == ci) {
                        float iw = fmaxf(fminf(xi2, x2[j]) - fmaxf(xi1, x1[j]), 0.f);
                        float ih = fmaxf(fminf(yi2, y2[j]) - fmaxf(yi1, y1[j]), 0.f);
                        float inter = iw * ih;
                        float iou = inter / fmaxf(ai + ar[j] - inter, 1e-6f);
                        if (iou > IOU_THR) kp[j] = 0;
                    }
                }
            }
            __syncthreads();
        }

        if (tid == 0) {
            int cnt = 0;
            for (int i = 0; i < m; i++) {
                if (kp[i]) {
                    if (cnt < Kn) idxs[cnt] = i;
                    cnt++;
                }
            }
            s_num = cnt < Kn ? cnt : Kn;
        }
    } else {
        if (tid == 0) s_num = 0;
    }
    __syncthreads();

    const int num = s_num;
    if (tid == 0) out[b] = (float)num;

    float* pb = out + Bn;                         // boxes
    float* ps = out + Bn + Bn * Kn * 4;           // scores
    float* pc = out + Bn + Bn * Kn * 4 + Bn * Kn; // classes
    for (int r = tid; r < Kn; r += 256) {
        float b0 = 0.f, b1 = 0.f, b2 = 0.f, b3 = 0.f, s = 0.f, cf = -1.0f;
        if (r < num) {
            int i = idxs[r];
            b0 = x1[i]; b1 = y1[i]; b2 = x2[i]; b3 = y2[i];
            s = sc[i]; cf = (float)cl[i];
        }
        size_t base = (size_t)(b * Kn + r);
        pb[base * 4 + 0] = b0;
        pb[base * 4 + 1] = b1;
        pb[base * 4 + 2] = b2;
        pb[base * 4 + 3] = b3;
        ps[base] = s;
        pc[base] = cf;
    }
}

// ---------------- launch ----------------
extern "C" void kernel_launch(void* const* d_in, const int* in_sizes, int n_in,
                              void* d_out, int out_size) {
    const float* tl_heat = (const float*)d_in[0];
    const float* br_heat = (const float*)d_in[1];
    const float* tl_off  = (const float*)d_in[2];
    const float* br_off  = (const float*)d_in[3];
    const float* tl_emb  = (const float*)d_in[4];
    const float* br_emb  = (const float*)d_in[5];
    const int*   inp_h   = (const int*)d_in[6];
    const int*   inp_w   = (const int*)d_in[7];
    float* out = (float*)d_out;

    cudaFuncSetAttribute(k_select, cudaFuncAttributeMaxDynamicSharedMemorySize,
                         16384 * 8 + 4096 * 4);
    cudaFuncSetAttribute(k_pair_nms, cudaFuncAttributeMaxDynamicSharedMemorySize, 16384 * 8);

    k_zero<<<1, 32>>>();
    k_localmax<<<2 * Bn * Cn, 256>>>(tl_heat, br_heat);
    k_select<<<SEGS, 1024, 16384 * 8 + 4096 * 4>>>(tl_off, br_off, tl_emb, br_emb, inp_h, inp_w);
    k_pair_nms<<<Bn, 256, 16384 * 8>>>(out);
}

// round 3
// speedup vs baseline: 9.4254x; 4.4352x over previous
#include <cuda_runtime.h>
#include <cstdint>

#define Bn 16
#define Cn 80
#define Hn 128
#define Wn 128
#define HWn 16384
#define Kn 100
#define NUMD 1000
#define SEGS 32
#define HI_CAP 65536
#define CAND_CAP 262144
#define SCORE_THR 0.05f
#define IOU_THR 0.5f
#define DIST_THR 0.5f
#define THR_HI 3.2f

typedef unsigned long long u64;
typedef unsigned int u32;

#define NEG_INF __int_as_float(0xff800000)

// ---------------- device scratch ----------------
__device__ u64 g_hi[SEGS][HI_CAP];      // high-tier candidates (raw >= THR_HI)
__device__ int g_cnt[SEGS];
__device__ u64 g_low[SEGS][CAND_CAP];   // slow-path full candidate list
__device__ int g_cnt_low[SEGS];

__device__ float g_top_s[SEGS][Kn];
__device__ float g_top_x[SEGS][Kn];
__device__ float g_top_y[SEGS][Kn];
__device__ float g_top_e[SEGS][Kn];
__device__ int   g_top_c[SEGS][Kn];

// ---------------- helpers ----------------
__device__ __forceinline__ u32 map_f(float f) {
    u32 u = __float_as_uint(f);
    return (u & 0x80000000u) ? ~u : (u | 0x80000000u);
}
__device__ __forceinline__ float sigmoidf_dev(float x) {
    if (x >= 0.f) return 1.f / (1.f + expf(-x));
    float e = expf(x);
    return e / (1.f + e);
}
__device__ __forceinline__ u64 make_key(float raw, u32 idx) {
    float s = sigmoidf_dev(raw);
    return ((u64)(__float_as_uint(s) | 0x80000000u) << 32) |
           (u64)(0xFFFFFFFFu - idx);
}

// ascending bitonic sort of n (power of 2) u64 keys in shared memory
__device__ __forceinline__ void bitonic_sort(u64* d, int n, int tid, int nt) {
    for (int k = 2; k <= n; k <<= 1) {
        for (int j = k >> 1; j > 0; j >>= 1) {
            for (int t = tid; t < n; t += nt) {
                int ixj = t ^ j;
                if (ixj > t) {
                    u64 a = d[t], b = d[ixj];
                    bool asc = ((t & k) == 0);
                    if ((a > b) == asc) { d[t] = b; d[ixj] = a; }
                }
            }
            __syncthreads();
        }
    }
}

// ---------------- K0: zero counters ----------------
__global__ void k_zero() {
    int t = threadIdx.x;
    if (t < SEGS) { g_cnt[t] = 0; g_cnt_low[t] = 0; }
}

// ---------------- K1: 3x3 local-max + threshold, register-rolling ----------------
// one block per (heat, b, c) plane; 256 threads = 8 warps x 16 rows each.
// Only candidates with raw >= THR_HI are appended (rare -> cheap atomics).
__global__ void k_localmax(const float* __restrict__ tl, const float* __restrict__ br) {
    const int plane = blockIdx.x;                // 0 .. 2*B*C-1
    const int h = plane / (Bn * Cn);
    const int rem = plane % (Bn * Cn);           // b*C + c
    const int b = rem / Cn;
    const int c = rem % Cn;
    const int seg = h * Bn + b;
    const float* src = (h == 0 ? tl : br) + (size_t)rem * HWn;

    const int warp = threadIdx.x >> 5;
    const int lane = threadIdx.x & 31;
    const int r0 = warp * 16;

    const float4* row4 = (const float4*)src;

    float4 vcur, vnext;
    float4 hprev, hcur, hnext;

    auto hmax4 = [&](float4 v) -> float4 {
        float left  = __shfl_up_sync(0xffffffffu, v.w, 1);
        float right = __shfl_down_sync(0xffffffffu, v.x, 1);
        if (lane == 0)  left  = NEG_INF;
        if (lane == 31) right = NEG_INF;
        float4 r;
        r.x = fmaxf(fmaxf(left, v.x), v.y);
        r.y = fmaxf(fmaxf(v.x, v.y), v.z);
        r.z = fmaxf(fmaxf(v.y, v.z), v.w);
        r.w = fmaxf(fmaxf(v.z, v.w), right);
        return r;
    };

    vcur = row4[r0 * 32 + lane];
    hcur = hmax4(vcur);
    if (r0 > 0) {
        float4 vp = row4[(r0 - 1) * 32 + lane];
        hprev = hmax4(vp);
    } else {
        hprev = make_float4(NEG_INF, NEG_INF, NEG_INF, NEG_INF);
    }

    for (int y = r0; y < r0 + 16; ++y) {
        if (y + 1 < Hn) {
            vnext = row4[(y + 1) * 32 + lane];
            hnext = hmax4(vnext);
        } else {
            hnext = make_float4(NEG_INF, NEG_INF, NEG_INF, NEG_INF);
        }

        // 3x3 max (incl. self) fused with threshold: flag <=> v == max9 && v >= THR
        float m0 = fmaxf(fmaxf(fmaxf(hprev.x, hcur.x), hnext.x), THR_HI);
        float m1 = fmaxf(fmaxf(fmaxf(hprev.y, hcur.y), hnext.y), THR_HI);
        float m2 = fmaxf(fmaxf(fmaxf(hprev.z, hcur.z), hnext.z), THR_HI);
        float m3 = fmaxf(fmaxf(fmaxf(hprev.w, hcur.w), hnext.w), THR_HI);
        bool f0 = vcur.x >= m0;
        bool f1 = vcur.y >= m1;
        bool f2 = vcur.z >= m2;
        bool f3 = vcur.w >= m3;
        bool any = f0 | f1 | f2 | f3;

        if (__ballot_sync(0xffffffffu, any)) {
            if (any) {
                u32 idx_base = (u32)(c * HWn + y * Wn + lane * 4);
                if (f0) {
                    int p = atomicAdd(&g_cnt[seg], 1);
                    if (p < HI_CAP) g_hi[seg][p] = make_key(vcur.x, idx_base + 0);
                }
                if (f1) {
                    int p = atomicAdd(&g_cnt[seg], 1);
                    if (p < HI_CAP) g_hi[seg][p] = make_key(vcur.y, idx_base + 1);
                }
                if (f2) {
                    int p = atomicAdd(&g_cnt[seg], 1);
                    if (p < HI_CAP) g_hi[seg][p] = make_key(vcur.z, idx_base + 2);
                }
                if (f3) {
                    int p = atomicAdd(&g_cnt[seg], 1);
                    if (p < HI_CAP) g_hi[seg][p] = make_key(vcur.w, idx_base + 3);
                }
            }
        }

        hprev = hcur; hcur = hnext; vcur = vnext;
    }
}

// ---------------- K2: per-segment top-100 select + gather ----------------
// 32 blocks, 1024 threads. Fast path: sort the small hi-tier list.
// Slow path (cnt<100 or overflow): recompute all maxima for this segment and
// run histogram + compact + sort (full correctness, never taken on normal data).
__global__ void k_select(const float* __restrict__ tl_heat, const float* __restrict__ br_heat,
                         const float* __restrict__ tl_off, const float* __restrict__ br_off,
                         const float* __restrict__ tl_emb, const float* __restrict__ br_emb,
                         const int* __restrict__ inp_h, const int* __restrict__ inp_w) {
    extern __shared__ unsigned char s4[];
    u64* comp = (u64*)s4;                 // 16384 u64
    u32* hist = (u32*)(comp + 16384);     // 4096 u32
    __shared__ int s_cut, s_cnt2, chunk[32], s_n2;

    const int seg = blockIdx.x;
    const int tid = threadIdx.x;
    const int hflag = seg / Bn;
    const int b = seg % Bn;
    const int mhi = g_cnt[seg];

    if (mhi >= Kn && mhi <= 16384) {
        // ---- fast path: hi-tier holds the true top-100 ----
        for (int i = tid; i < mhi; i += 1024) comp[i] = g_hi[seg][i];
        int n2 = 128;
        while (n2 < mhi) n2 <<= 1;
        for (int t = mhi + tid; t < n2; t += 1024) comp[t] = 0ull;
        if (tid == 0) s_n2 = n2;
        __syncthreads();
        bitonic_sort(comp, n2, tid, 1024);
    } else {
        // ---- slow path: recompute all local maxima (no threshold) ----
        const float* heat = (hflag ? br_heat : tl_heat) + (size_t)(b * Cn) * HWn;
        for (int e = tid; e < Cn * HWn; e += 1024) {
            int cc = e >> 14;
            int ind = e & (HWn - 1);
            int y = ind >> 7, x = ind & 127;
            const float* pl = heat + (size_t)cc * HWn;
            float v = pl[ind];
            int y0 = y > 0 ? y - 1 : 0, y1 = y < 127 ? y + 1 : 127;
            int x0 = x > 0 ? x - 1 : 0, x1 = x < 127 ? x + 1 : 127;
            bool mx = true;
            for (int yy = y0; yy <= y1; ++yy)
                for (int xx = x0; xx <= x1; ++xx)
                    mx &= (v >= pl[yy * Wn + xx]);
            if (mx) {
                int p = atomicAdd(&g_cnt_low[seg], 1);
                if (p < CAND_CAP) g_low[seg][p] = make_key(v, (u32)(cc * HWn + ind));
            }
        }
        __syncthreads();

        const int Mc0 = g_cnt_low[seg];
        const int Mc = Mc0 < CAND_CAP ? Mc0 : CAND_CAP;

        for (int i = tid; i < 4096; i += 1024) hist[i] = 0;
        if (tid == 0) s_cnt2 = 0;
        __syncthreads();

        for (int i = tid; i < Mc; i += 1024)
            atomicAdd(&hist[(u32)(g_low[seg][i] >> 52)], 1u);
        __syncthreads();

        if (tid < 32) {
            int s = 0;
            for (int i = 0; i < 128; i++) s += hist[tid * 128 + i];
            chunk[tid] = s;
        }
        __syncthreads();
        if (tid == 0) {
            int acc = 0, T = 0, w;
            for (w = 31; w >= 0; --w) {
                if (acc + chunk[w] >= Kn) break;
                acc += chunk[w];
            }
            if (w >= 0) {
                for (int bin = w * 128 + 127; bin >= w * 128; --bin) {
                    acc += hist[bin];
                    if (acc >= Kn) { T = bin; break; }
                }
            }
            s_cut = T;
        }
        __syncthreads();
        const u32 T = (u32)s_cut;

        for (int i = tid; i < Mc; i += 1024) {
            u64 key = g_low[seg][i];
            if ((u32)(key >> 52) >= T) {
                int pos = atomicAdd(&s_cnt2, 1);
                if (pos < 16384) comp[pos] = key;
            }
        }
        __syncthreads();

        int cnt2 = s_cnt2 < 16384 ? s_cnt2 : 16384;
        int n2 = 128;
        while (n2 < cnt2) n2 <<= 1;
        for (int t = cnt2 + tid; t < n2; t += 1024) comp[t] = 0ull;
        if (tid == 0) s_n2 = n2;
        __syncthreads();
        bitonic_sort(comp, n2, tid, 1024);
    }

    const int n2 = s_n2;
    if (tid < Kn) {
        u64 key = comp[n2 - 1 - tid];
        u32 m = (u32)(key >> 32);
        float score = __uint_as_float(m & 0x7FFFFFFFu);
        u32 idx = 0xFFFFFFFFu - (u32)(key & 0xFFFFFFFFu);
        int cls = idx / HWn;
        int ind = idx % HWn;
        int yy = ind >> 7, xx = ind & 127;
        const float* offp = hflag ? br_off : tl_off;
        const float* embp = hflag ? br_emb : tl_emb;
        float ox = offp[((size_t)(b * 2 + 0) * HWn) + ind];
        float oy = offp[((size_t)(b * 2 + 1) * HWn) + ind];
        float em = embp[(size_t)b * HWn + ind];
        float wr = (float)(*inp_w) / (float)Wn;
        float hr = (float)(*inp_h) / (float)Hn;
        float xs = fmaxf(((float)xx + ox) * wr, 0.f);
        float ys = fmaxf(((float)yy + oy) * hr, 0.f);
        g_top_s[seg][tid] = score;
        g_top_x[seg][tid] = xs;
        g_top_y[seg][tid] = ys;
        g_top_e[seg][tid] = em;
        g_top_c[seg][tid] = cls;
    }
}

// ---------------- K3: pairing + compact positives + sort + NMS + output ----------------
__global__ void k_pair_nms(float* __restrict__ out) {
    extern __shared__ u64 pos[];  // 16384 capacity
    __shared__ float ts[Kn], tx[Kn], ty[Kn], te[Kn];
    __shared__ float bs_[Kn], bx[Kn], by[Kn], be[Kn];
    __shared__ int tc[Kn], bc[Kn];
    __shared__ int s_np;

    __shared__ float x1[NUMD], y1[NUMD], x2[NUMD], y2[NUMD], sc[NUMD], ar[NUMD];
    __shared__ int cl[NUMD];
    __shared__ unsigned char kp[NUMD];
    __shared__ int idxs[Kn];
    __shared__ int s_num;

    const int b = blockIdx.x;
    const int tid = threadIdx.x;

    if (tid < Kn) {
        int st = b, sb = Bn + b;
        ts[tid] = g_top_s[st][tid]; tx[tid] = g_top_x[st][tid];
        ty[tid] = g_top_y[st][tid]; te[tid] = g_top_e[st][tid];
        tc[tid] = g_top_c[st][tid];
        bs_[tid] = g_top_s[sb][tid]; bx[tid] = g_top_x[sb][tid];
        by[tid] = g_top_y[sb][tid]; be[tid] = g_top_e[sb][tid];
        bc[tid] = g_top_c[sb][tid];
    }
    if (tid == 0) s_np = 0;
    __syncthreads();

    for (int t = tid; t < Kn * Kn; t += 256) {
        int i = t / Kn, j = t % Kn;
        float scv = (ts[i] + bs_[j]) * 0.5f;
        bool neg = (tc[i] != bc[j]) || (bx[j] <= tx[i]) || (by[j] <= ty[i]) ||
                   (fabsf(te[i] - be[j]) > DIST_THR);
        if (!neg && scv > SCORE_THR) {
            int p = atomicAdd(&s_np, 1);
            if (p < 16384)
                pos[p] = ((u64)map_f(scv) << 32) | (u64)(0xFFFFFFFFu - (u32)t);
        }
    }
    __syncthreads();

    int np = s_np < 16384 ? s_np : 16384;
    if (np > 0) {
        int n2 = 2;
        while (n2 < np) n2 <<= 1;
        for (int t = np + tid; t < n2; t += 256) pos[t] = 0ull;
        __syncthreads();
        bitonic_sort(pos, n2, tid, 256);

        int m = np < NUMD ? np : NUMD;
        for (int r = tid; r < m; r += 256) {
            u64 key = pos[n2 - 1 - r];
            u32 mm = (u32)(key >> 32);
            float scv = __uint_as_float(mm & 0x7FFFFFFFu);
            u32 t = 0xFFFFFFFFu - (u32)(key & 0xFFFFFFFFu);
            int i = t / Kn, j = t % Kn;
            float a0 = tx[i], a1 = ty[i], a2 = bx[j], a3 = by[j];
            x1[r] = a0; y1[r] = a1; x2[r] = a2; y2[r] = a3;
            sc[r] = scv;
            cl[r] = tc[i];
            kp[r] = 1;
            ar[r] = fmaxf(a2 - a0, 0.f) * fmaxf(a3 - a1, 0.f);
        }
        __syncthreads();

        for (int i = 0; i < m; i++) {
            if (kp[i]) {
                float xi1 = x1[i], yi1 = y1[i], xi2 = x2[i], yi2 = y2[i], ai = ar[i];
                int ci = cl[i];
                for (int j = i + 1 + tid; j < m; j += 256) {
                    if (kp[j] && cl[j] == ci) {
                        float iw = fmaxf(fminf(xi2, x2[j]) - fmaxf(xi1, x1[j]), 0.f);
                        float ih = fmaxf(fminf(yi2, y2[j]) - fmaxf(yi1, y1[j]), 0.f);
                        float inter = iw * ih;
                        float iou = inter / fmaxf(ai + ar[j] - inter, 1e-6f);
                        if (iou > IOU_THR) kp[j] = 0;
                    }
                }
            }
            __syncthreads();
        }

        if (tid == 0) {
            int cnt = 0;
            for (int i = 0; i < m; i++) {
                if (kp[i]) {
                    if (cnt < Kn) idxs[cnt] = i;
                    cnt++;
                }
            }
            s_num = cnt < Kn ? cnt : Kn;
        }
    } else {
        if (tid == 0) s_num = 0;
    }
    __syncthreads();

    const int num = s_num;
    if (tid == 0) out[b] = (float)num;

    float* pb = out + Bn;                         // boxes
    float* ps = out + Bn + Bn * Kn * 4;           // scores
    float* pc = out + Bn + Bn * Kn * 4 + Bn * Kn; // classes
    for (int r = tid; r < Kn; r += 256) {
        float b0 = 0.f, b1 = 0.f, b2 = 0.f, b3 = 0.f, s = 0.f, cf = -1.0f;
        if (r < num) {
            int i = idxs[r];
            b0 = x1[i]; b1 = y1[i]; b2 = x2[i]; b3 = y2[i];
            s = sc[i]; cf = (float)cl[i];
        }
        size_t base = (size_t)(b * Kn + r);
        pb[base * 4 + 0] = b0;
        pb[base * 4 + 1] = b1;
        pb[base * 4 + 2] = b2;
        pb[base * 4 + 3] = b3;
        ps[base] = s;
        pc[base] = cf;
    }
}

// ---------------- launch ----------------
extern "C" void kernel_launch(void* const* d_in, const int* in_sizes, int n_in,
                              void* d_out, int out_size) {
    const float* tl_heat = (const float*)d_in[0];
    const float* br_heat = (const float*)d_in[1];
    const float* tl_off  = (const float*)d_in[2];
    const float* br_off  = (const float*)d_in[3];
    const float* tl_emb  = (const float*)d_in[4];
    const float* br_emb  = (const float*)d_in[5];
    const int*   inp_h   = (const int*)d_in[6];
    const int*   inp_w   = (const int*)d_in[7];
    float* out = (float*)d_out;

    cudaFuncSetAttribute(k_select, cudaFuncAttributeMaxDynamicSharedMemorySize,
                         16384 * 8 + 4096 * 4);
    cudaFuncSetAttribute(k_pair_nms, cudaFuncAttributeMaxDynamicSharedMemorySize, 16384 * 8);

    k_zero<<<1, 32>>>();
    k_localmax<<<2 * Bn * Cn, 256>>>(tl_heat, br_heat);
    k_select<<<SEGS, 1024, 16384 * 8 + 4096 * 4>>>(tl_heat, br_heat, tl_off, br_off,
                                                   tl_emb, br_emb, inp_h, inp_w);
    k_pair_nms<<<Bn, 256, 16384 * 8>>>(out);
}